// round 16
// baseline (speedup 1.0000x reference)
#include <cuda_runtime.h>
#include <cuda_fp16.h>
#include <cstdint>

#define NSAMPLES   524288
#define NFEAT      64
#define NGATES     64
#define NOUT       8
#define BASEN      66            // NFEAT + const0 + const1
#define MAXCONN    130
#define BLK        128
#define ROWB       256           // bytes per row: 128 samples * 2B (fp16)
#define SLOTS      88            // rows: 0 trash, 1 c0, 2 c1, 3.. live
#define SMEM_FAST  (SLOTS * ROWB)    // 22528 B -> 10 blocks/SM = 40 warps
#define NT         (NSAMPLES / BLK)  // 4096 blocks

struct Params {
    uint4    gd[NGATES];     // {offA, offB, offStore, 0} compact byte offsets
    uint2    eorig[NGATES];  // raw entry indices (in-kernel fallback)
    uint4    xoff4[16];      // X row byte offsets, 4 features per entry
    unsigned flags;          // 1 = capacity overflow -> fallback branch
    unsigned pad[3];
    float    w[NGATES][NOUT];// output_weights * output_scale (pre-folded)
};
__device__   Params g_stage;
__constant__ Params c_p;

// Lexicographic (value desc, index asc) top-2 insert — reproduces top_k's
// lower-index-wins tie-break (softmax monotonic => top-2 of raw logits).
static __device__ __forceinline__ void ins2(float v, int j,
                                            float& v1, int& i1,
                                            float& v2, int& i2) {
    if (v > v1 || (v == v1 && j < i1)) { v2 = v1; i2 = i1; v1 = v; i1 = j; }
    else if (v > v2 || (v == v2 && j < i2)) { v2 = v; i2 = j; }
}

// ---------------------------------------------------------------------------
// prep (ONE kernel, 1 block x 1024 threads): 16 threads/gate top-2 (R8-proven)
// -> ballot/popc slot compaction (R14/R15-proven) -> descriptors + weights.
// ---------------------------------------------------------------------------
__global__ void __launch_bounds__(1024)
prep_kernel(const float* __restrict__ gw,
            const float* __restrict__ ow,
            const float* __restrict__ sc) {
    __shared__ int si1[NGATES], si2[NGATES];
    __shared__ int slotArr[MAXCONN];
    __shared__ unsigned char needf[MAXCONN];
    const int tid  = threadIdx.x;
    const int gate = tid >> 4;
    const int lane = tid & 15;

    if (tid < MAXCONN) needf[tid] = 0;

    {   // top-2 of gate_weights[gate, 0 : 66+gate]
        const float* row = gw + gate * MAXCONN;
        const int n = BASEN + gate;
        float v1 = -3.4e38f, v2 = -3.4e38f;
        int   i1 = 0x7fffffff, i2 = 0x7fffffff;
#pragma unroll
        for (int k = 0; k < (MAXCONN + 15) / 16; ++k) {
            int j = lane + k * 16;
            if (j < n) ins2(row[j], j, v1, i1, v2, i2);
        }
#pragma unroll
        for (int d = 8; d >= 1; d >>= 1) {
            float ov1 = __shfl_down_sync(0xffffffffu, v1, d);
            int   oi1 = __shfl_down_sync(0xffffffffu, i1, d);
            float ov2 = __shfl_down_sync(0xffffffffu, v2, d);
            int   oi2 = __shfl_down_sync(0xffffffffu, i2, d);
            ins2(ov1, oi1, v1, i1, v2, i2);
            ins2(ov2, oi2, v1, i1, v2, i2);
        }
        if (lane == 0) { si1[gate] = i1; si2[gate] = i2; }
    }
    __syncthreads();
    if (tid < NGATES) { needf[si1[tid]] = 1; needf[si2[tid]] = 1; }
    __syncthreads();

    if (tid < 32) {                      // single-pool prefix compaction
        int running = 3;                 // rows 0/1/2 reserved
        for (int ch = 0; ch < 5; ++ch) {
            int e = ch * 32 + tid;
            bool nd = (e < MAXCONN) && needf[e] && (e != 64) && (e != 65);
            unsigned mask = __ballot_sync(0xffffffffu, nd);
            if (e < MAXCONN) {
                int s;
                if      (e == 64) s = 1;
                else if (e == 65) s = 2;
                else if (nd)      s = running + __popc(mask & ((1u << tid) - 1u));
                else              s = 0;               // dead -> trash row
                slotArr[e] = s;
            }
            running += __popc(mask);
        }
        if (tid == 0) g_stage.flags = (running > SLOTS) ? 1u : 0u;
    }
    __syncthreads();

    if (tid < NGATES) {
        int e1 = si1[tid], e2 = si2[tid];
        g_stage.gd[tid] = make_uint4((unsigned)(slotArr[e1] * ROWB),
                                     (unsigned)(slotArr[e2] * ROWB),
                                     (unsigned)(slotArr[BASEN + tid] * ROWB), 0u);
        g_stage.eorig[tid] = make_uint2((unsigned)e1, (unsigned)e2);
    }
    if (tid < 16)
        g_stage.xoff4[tid] = make_uint4((unsigned)(slotArr[4 * tid + 0] * ROWB),
                                        (unsigned)(slotArr[4 * tid + 1] * ROWB),
                                        (unsigned)(slotArr[4 * tid + 2] * ROWB),
                                        (unsigned)(slotArr[4 * tid + 3] * ROWB));
    if (tid < NGATES * NOUT) {
        int i = tid >> 3, j = tid & 7;
        g_stage.w[i][j] = ow[i * NOUT + j] * sc[j];
    }
}

// ---------------------------------------------------------------------------
// Fast kernel: fp16 compacted buffer (88 x 256 B = 22.5 KB -> 10 blocks/SM,
// 40 warps), 1 sample/thread, EXACT R4/R14 gate-loop shape (post-STS
// prefetch-1, zero fixups, LDC.128 tables, trash-row always-store). Compute
// fp32, store fp16 (R8-proven error budget). Warp row accesses are 64 B
// contiguous -> conflict-free without padding. In-kernel guarded fallback
// (local-array, 1 thread = 1 sample) covers capacity overflow.
// ---------------------------------------------------------------------------
__global__ void __launch_bounds__(BLK, 10)
fast_kernel(const float* __restrict__ X, float* __restrict__ out) {
    const int tid = threadIdx.x;
    const long long base = (long long)blockIdx.x * BLK;

    if (c_p.flags) {                     // overflow fallback (never, here)
        const long long s = base + tid;
        float buf[MAXCONN];
        const float* xr = X + s * NFEAT;
#pragma unroll
        for (int f = 0; f < NFEAT; ++f) buf[f] = xr[f];
        buf[64] = 0.0f; buf[65] = 1.0f;
        float acc[NOUT];
#pragma unroll
        for (int j = 0; j < NOUT; ++j) acc[j] = 0.0f;
        for (int i = 0; i < NGATES; ++i) {
            uint2 o = c_p.eorig[i];
            float g = fmaf(-buf[o.x], buf[o.y], 1.0f);
            buf[BASEN + i] = g;
#pragma unroll
            for (int j = 0; j < NOUT; ++j)
                acc[j] = fmaf(g, c_p.w[i][j], acc[j]);
        }
        float4* op = (float4*)(out + s * NOUT);
        op[0] = make_float4(acc[0], acc[1], acc[2], acc[3]);
        op[1] = make_float4(acc[4], acc[5], acc[6], acc[7]);
        return;
    }

    extern __shared__ char sb[];

    // X transpose into compact fp16 rows. Element i = 512k + 4tid:
    //   sample s = 8k + (tid>>4), features f..f+3 with f = 4*(tid&15).
    const uint4 xo = c_p.xoff4[tid & 15];     // per-thread row offsets (once)
    const int h = tid >> 4;
    const float4* Xb = (const float4*)(X + base * NFEAT);
#pragma unroll
    for (int k = 0; k < 16; ++k) {
        float4 v = __ldcs(&Xb[k * BLK + tid]);
        unsigned so = 2u * (unsigned)(8 * k + h);       // sample byte offset
        *(__half*)(sb + xo.x + so) = __float2half_rn(v.x);
        *(__half*)(sb + xo.y + so) = __float2half_rn(v.y);
        *(__half*)(sb + xo.z + so) = __float2half_rn(v.z);
        *(__half*)(sb + xo.w + so) = __float2half_rn(v.w);
    }
    *(__half*)(sb + 1 * ROWB + 2 * tid) = __float2half_rn(0.0f);  // const 0
    *(__half*)(sb + 2 * ROWB + 2 * tid) = __float2half_rn(1.0f);  // const 1
    __syncthreads();

    char* col = sb + 2u * tid;           // this sample's byte column
    float acc[NOUT];
#pragma unroll
    for (int j = 0; j < NOUT; ++j) acc[j] = 0.0f;

    uint4 d = c_p.gd[0];
    float a = __half2float(*(const __half*)(col + d.x));
    float b = __half2float(*(const __half*)(col + d.y));

#pragma unroll
    for (int i = 0; i < NGATES; ++i) {
        float g = fmaf(-a, b, 1.0f);                    // g = 1 - a*b
        *(__half*)(col + d.z) = __float2half_rn(g);     // STS (trash if dead)

        if (i + 1 < NGATES) {                           // post-STS prefetch
            uint4 dn = c_p.gd[i + 1];                   //  -> never stale
            a = __half2float(*(const __half*)(col + dn.x));
            b = __half2float(*(const __half*)(col + dn.y));
            d = dn;
        }

        float4 w0 = *(const float4*)&c_p.w[i][0];       // 2x LDC.128
        float4 w1 = *(const float4*)&c_p.w[i][4];
        acc[0] = fmaf(g, w0.x, acc[0]);
        acc[1] = fmaf(g, w0.y, acc[1]);
        acc[2] = fmaf(g, w0.z, acc[2]);
        acc[3] = fmaf(g, w0.w, acc[3]);
        acc[4] = fmaf(g, w1.x, acc[4]);
        acc[5] = fmaf(g, w1.y, acc[5]);
        acc[6] = fmaf(g, w1.z, acc[6]);
        acc[7] = fmaf(g, w1.w, acc[7]);
    }

    float4* op = (float4*)(out + (base + tid) * NOUT);
    __stcs(&op[0], make_float4(acc[0], acc[1], acc[2], acc[3]));
    __stcs(&op[1], make_float4(acc[4], acc[5], acc[6], acc[7]));
}

// ---------------------------------------------------------------------------
// Launch: prep -> ONE memcpy -> fast (3 nodes; fallback is an in-kernel branch)
// ---------------------------------------------------------------------------
extern "C" void kernel_launch(void* const* d_in, const int* in_sizes, int n_in,
                              void* d_out, int out_size) {
    const float* X  = (const float*)d_in[0];  // (524288, 64)
    const float* gw = (const float*)d_in[1];  // (64, 130)
    const float* ow = (const float*)d_in[2];  // (64, 8)
    const float* sc = (const float*)d_in[3];  // (8,)
    float* out = (float*)d_out;               // (524288, 8)

    cudaFuncSetAttribute((const void*)fast_kernel,
                         cudaFuncAttributeMaxDynamicSharedMemorySize, SMEM_FAST);

    prep_kernel<<<1, 1024>>>(gw, ow, sc);

    void* gp = nullptr;
    cudaGetSymbolAddress(&gp, g_stage);
    cudaMemcpyToSymbolAsync(c_p, gp, sizeof(Params), 0,
                            cudaMemcpyDeviceToDevice, 0);

    fast_kernel<<<NT, BLK, SMEM_FAST>>>(X, out);
}

// round 17
// speedup vs baseline: 1.4939x; 1.4939x over previous
#include <cuda_runtime.h>
#include <cstdint>

#define NSAMPLES   524288
#define NFEAT      64
#define NGATES     64
#define NOUT       8
#define BASEN      66            // NFEAT + const0 + const1
#define MAXCONN    130
#define BLK        128
#define STRIDEF    129           // floats per row (odd -> conflict-free)
#define ROWB       (STRIDEF * 4) // 516 B per row
#define SLOTS      88            // rows: 0 trash, 1 c0, 2 c1, 3.. live
#define SMEM_FAST  (SLOTS * ROWB)    // 45408 B -> 5 blocks/SM = 20 warps
#define NT         (NSAMPLES / BLK)  // 4096 blocks

struct Params {
    uint4    gd[NGATES];     // {offA, offB, offStore, 0} compact byte offsets
    uint2    eorig[NGATES];  // raw entry indices (in-kernel fallback)
    uint4    xoff4[16];      // X row byte offsets, 4 features per entry
    unsigned flags;          // 1 = capacity overflow -> fallback branch
    unsigned pad[3];
    float    w[NGATES][NOUT];// output_weights * output_scale (pre-folded)
};
__device__   Params g_stage;
__constant__ Params c_p;

// Lexicographic (value desc, index asc) top-2 insert — reproduces top_k's
// lower-index-wins tie-break (softmax monotonic => top-2 of raw logits).
static __device__ __forceinline__ void ins2(float v, int j,
                                            float& v1, int& i1,
                                            float& v2, int& i2) {
    if (v > v1 || (v == v1 && j < i1)) { v2 = v1; i2 = i1; v1 = v; i1 = j; }
    else if (v > v2 || (v == v2 && j < i2)) { v2 = v; i2 = j; }
}

// ---------------------------------------------------------------------------
// prep (ONE kernel, 1 block x 1024 threads): 16 threads/gate top-2 (R8/R16-
// proven) -> ballot/popc slot compaction (R14/R15-proven) -> descriptors +
// scale-folded weights into global staging.
// ---------------------------------------------------------------------------
__global__ void __launch_bounds__(1024)
prep_kernel(const float* __restrict__ gw,
            const float* __restrict__ ow,
            const float* __restrict__ sc) {
    __shared__ int si1[NGATES], si2[NGATES];
    __shared__ int slotArr[MAXCONN];
    __shared__ unsigned char needf[MAXCONN];
    const int tid  = threadIdx.x;
    const int gate = tid >> 4;
    const int lane = tid & 15;

    if (tid < MAXCONN) needf[tid] = 0;

    {   // top-2 of gate_weights[gate, 0 : 66+gate]
        const float* row = gw + gate * MAXCONN;
        const int n = BASEN + gate;
        float v1 = -3.4e38f, v2 = -3.4e38f;
        int   i1 = 0x7fffffff, i2 = 0x7fffffff;
#pragma unroll
        for (int k = 0; k < (MAXCONN + 15) / 16; ++k) {
            int j = lane + k * 16;
            if (j < n) ins2(row[j], j, v1, i1, v2, i2);
        }
#pragma unroll
        for (int d = 8; d >= 1; d >>= 1) {
            float ov1 = __shfl_down_sync(0xffffffffu, v1, d);
            int   oi1 = __shfl_down_sync(0xffffffffu, i1, d);
            float ov2 = __shfl_down_sync(0xffffffffu, v2, d);
            int   oi2 = __shfl_down_sync(0xffffffffu, i2, d);
            ins2(ov1, oi1, v1, i1, v2, i2);
            ins2(ov2, oi2, v1, i1, v2, i2);
        }
        if (lane == 0) { si1[gate] = i1; si2[gate] = i2; }
    }
    __syncthreads();
    if (tid < NGATES) { needf[si1[tid]] = 1; needf[si2[tid]] = 1; }
    __syncthreads();

    if (tid < 32) {                      // single-pool prefix compaction
        int running = 3;                 // rows 0/1/2 reserved
        for (int ch = 0; ch < 5; ++ch) {
            int e = ch * 32 + tid;
            bool nd = (e < MAXCONN) && needf[e] && (e != 64) && (e != 65);
            unsigned mask = __ballot_sync(0xffffffffu, nd);
            if (e < MAXCONN) {
                int s;
                if      (e == 64) s = 1;
                else if (e == 65) s = 2;
                else if (nd)      s = running + __popc(mask & ((1u << tid) - 1u));
                else              s = 0;               // dead -> trash row
                slotArr[e] = s;
            }
            running += __popc(mask);
        }
        if (tid == 0) g_stage.flags = (running > SLOTS) ? 1u : 0u;
    }
    __syncthreads();

    if (tid < NGATES) {
        int e1 = si1[tid], e2 = si2[tid];
        g_stage.gd[tid] = make_uint4((unsigned)(slotArr[e1] * ROWB),
                                     (unsigned)(slotArr[e2] * ROWB),
                                     (unsigned)(slotArr[BASEN + tid] * ROWB), 0u);
        g_stage.eorig[tid] = make_uint2((unsigned)e1, (unsigned)e2);
    }
    if (tid < 16)
        g_stage.xoff4[tid] = make_uint4((unsigned)(slotArr[4 * tid + 0] * ROWB),
                                        (unsigned)(slotArr[4 * tid + 1] * ROWB),
                                        (unsigned)(slotArr[4 * tid + 2] * ROWB),
                                        (unsigned)(slotArr[4 * tid + 3] * ROWB));
    if (tid < NGATES * NOUT) {
        int i = tid >> 3, j = tid & 7;
        g_stage.w[i][j] = ow[i * NOUT + j] * sc[j];
    }
}

// ---------------------------------------------------------------------------
// Fast kernel (R14 byte-for-byte — measured ~36 us): fp32 compacted buffer
// (88 x 516 B = 45.4 KB -> 5 blocks/SM, 20 warps), 1 sample/thread, exact R4
// gate loop (post-STS prefetch-1, zero fixups, LDC.128 tables, trash-row
// always-store). In-kernel guarded fallback covers capacity overflow.
// ---------------------------------------------------------------------------
__global__ void __launch_bounds__(BLK, 5)
fast_kernel(const float* __restrict__ X, float* __restrict__ out) {
    const int tid = threadIdx.x;
    const long long base = (long long)blockIdx.x * BLK;

    if (c_p.flags) {                     // overflow fallback (never, here)
        const long long s = base + tid;
        float buf[MAXCONN];
        const float* xr = X + s * NFEAT;
#pragma unroll
        for (int f = 0; f < NFEAT; ++f) buf[f] = xr[f];
        buf[64] = 0.0f; buf[65] = 1.0f;
        float acc[NOUT];
#pragma unroll
        for (int j = 0; j < NOUT; ++j) acc[j] = 0.0f;
        for (int i = 0; i < NGATES; ++i) {
            uint2 o = c_p.eorig[i];
            float g = fmaf(-buf[o.x], buf[o.y], 1.0f);
            buf[BASEN + i] = g;
#pragma unroll
            for (int j = 0; j < NOUT; ++j)
                acc[j] = fmaf(g, c_p.w[i][j], acc[j]);
        }
        float4* op = (float4*)(out + s * NOUT);
        op[0] = make_float4(acc[0], acc[1], acc[2], acc[3]);
        op[1] = make_float4(acc[4], acc[5], acc[6], acc[7]);
        return;
    }

    extern __shared__ float sbuf[];
    char* sb = (char*)sbuf;

    // X transpose into compact rows. Element i = 512k + 4tid:
    //   sample s = 8k + (tid>>4), features f..f+3 with f = 4*(tid&15).
    const uint4 xo = c_p.xoff4[tid & 15];     // per-thread row offsets (once)
    const int h = tid >> 4;
    const float4* Xb = (const float4*)(X + base * NFEAT);
#pragma unroll
    for (int k = 0; k < 16; ++k) {
        float4 v = __ldcs(&Xb[k * BLK + tid]);
        unsigned so = 4u * (unsigned)(8 * k + h);       // sample byte offset
        *(float*)(sb + xo.x + so) = v.x;
        *(float*)(sb + xo.y + so) = v.y;
        *(float*)(sb + xo.z + so) = v.z;
        *(float*)(sb + xo.w + so) = v.w;
    }
    sbuf[1 * STRIDEF + tid] = 0.0f;   // const 0 row
    sbuf[2 * STRIDEF + tid] = 1.0f;   // const 1 row
    __syncthreads();

    char* col = sb + 4u * tid;        // this sample's byte column
    float acc[NOUT];
#pragma unroll
    for (int j = 0; j < NOUT; ++j) acc[j] = 0.0f;

    uint4 d = c_p.gd[0];
    float a = *(const float*)(col + d.x);
    float b = *(const float*)(col + d.y);

#pragma unroll
    for (int i = 0; i < NGATES; ++i) {
        float g = fmaf(-a, b, 1.0f);               // g = 1 - a*b
        *(float*)(col + d.z) = g;                  // STS (trash row if dead)

        if (i + 1 < NGATES) {                      // post-STS prefetch
            uint4 dn = c_p.gd[i + 1];              //  -> never stale
            a = *(const float*)(col + dn.x);
            b = *(const float*)(col + dn.y);
            d = dn;
        }

        float4 w0 = *(const float4*)&c_p.w[i][0];  // 2x LDC.128
        float4 w1 = *(const float4*)&c_p.w[i][4];
        acc[0] = fmaf(g, w0.x, acc[0]);
        acc[1] = fmaf(g, w0.y, acc[1]);
        acc[2] = fmaf(g, w0.z, acc[2]);
        acc[3] = fmaf(g, w0.w, acc[3]);
        acc[4] = fmaf(g, w1.x, acc[4]);
        acc[5] = fmaf(g, w1.y, acc[5]);
        acc[6] = fmaf(g, w1.z, acc[6]);
        acc[7] = fmaf(g, w1.w, acc[7]);
    }

    float4* op = (float4*)(out + (base + tid) * NOUT);
    __stcs(&op[0], make_float4(acc[0], acc[1], acc[2], acc[3]));
    __stcs(&op[1], make_float4(acc[4], acc[5], acc[6], acc[7]));
}

// ---------------------------------------------------------------------------
// Launch: prep -> ONE memcpy -> fast (3 nodes; fallback is an in-kernel branch)
// ---------------------------------------------------------------------------
extern "C" void kernel_launch(void* const* d_in, const int* in_sizes, int n_in,
                              void* d_out, int out_size) {
    const float* X  = (const float*)d_in[0];  // (524288, 64)
    const float* gw = (const float*)d_in[1];  // (64, 130)
    const float* ow = (const float*)d_in[2];  // (64, 8)
    const float* sc = (const float*)d_in[3];  // (8,)
    float* out = (float*)d_out;               // (524288, 8)

    cudaFuncSetAttribute((const void*)fast_kernel,
                         cudaFuncAttributeMaxDynamicSharedMemorySize, SMEM_FAST);

    prep_kernel<<<1, 1024>>>(gw, ow, sc);

    void* gp = nullptr;
    cudaGetSymbolAddress(&gp, g_stage);
    cudaMemcpyToSymbolAsync(c_p, gp, sizeof(Params), 0,
                            cudaMemcpyDeviceToDevice, 0);

    fast_kernel<<<NT, BLK, SMEM_FAST>>>(X, out);
}